// round 7
// baseline (speedup 1.0000x reference)
#include <cuda_runtime.h>
#include <cstdint>

#define NC       32
#define NSTEPS   32
#define DDIM     30
#define BLOCK    128
#define PPT      8     // points per thread (independent chains for ILP)

// float2 table replicated over 16 lane-slots: tab[cell][lane&15] = (T00,T01).
// Entry 8B, lane-slot stride 8B, cell stride 128B, table 4KB.
// addr = base4K | (lane&15)<<3 | cell<<7  (single LOP3 after clamp+mask).
#define TAB_FLTS    (NC * 16 * 2)     // 1024 floats = 4KB
#define SLACK_FLTS  1024              // 4KB slack for runtime 4096-alignment

__global__ __launch_bounds__(BLOCK)
void cpab_kernel(const float* __restrict__ points,
                 const float* __restrict__ theta,
                 const float* __restrict__ basis,
                 float* __restrict__ out,
                 int n_points)
{
    __shared__ float sbuf[TAB_FLTS + SLACK_FLTS];
    __shared__ float s0[NC];
    __shared__ float s1[NC];

    const int t   = blockIdx.y;
    const int tid = threadIdx.x;

    // Runtime 4096-aligned table base in shared address space.
    uint32_t sbase = (uint32_t)__cvta_generic_to_shared(sbuf);
    uint32_t abase = (sbase + 4095u) & ~4095u;
    // Per-thread constant: base | (lane&15)*8. Slot bits [6:3] disjoint from
    // the cell field (bits [11:7]) and from the aligned base (bits >= 12).
    uint32_t C = abase | ((uint32_t)(tid & 15) << 3);

    // --- 32 per-cell step transforms for this theta ---
    if (tid < NC) {
        const float dT = 1.0f / (float)NSTEPS;
        const float* __restrict__ ba = basis + (2 * tid)     * DDIM;
        const float* __restrict__ bb = basis + (2 * tid + 1) * DDIM;
        const float* __restrict__ th = theta + t * DDIM;
        float a = 0.0f, b = 0.0f;
        #pragma unroll
        for (int j = 0; j < DDIM; ++j) {
            float tj = th[j];
            a = fmaf(ba[j], tj, a);
            b = fmaf(bb[j], tj, b);
        }
        a *= dT;
        b *= dT;
        float ea  = expf(a);
        float phi = (fabsf(a) < 1e-6f) ? (1.0f + 0.5f * a) : (expm1f(a) / a);
        s0[tid] = ea;
        s1[tid] = b * phi;
    }
    __syncthreads();

    // Replicate into the 16-slot float2 layout (conflict-free per LDS.64 phase).
    {
        float2* tab = (float2*)(sbuf + ((abase - sbase) >> 2));
        #pragma unroll
        for (int i = tid; i < NC * 16; i += BLOCK) {
            int cell = i >> 4;
            tab[i] = make_float2(s0[cell], s1[cell]);
        }
    }
    __syncthreads();

    // --- Main integration: 8 independent chains per thread ---
    const int base = blockIdx.x * (BLOCK * PPT) + tid;

    float x[PPT];
    #pragma unroll
    for (int k = 0; k < PPT; ++k) {
        int idx = base + k * BLOCK;
        x[k] = (idx < n_points) ? points[idx] : 0.0f;
    }

    #pragma unroll 4
    for (int s = 0; s < NSTEPS; ++s) {
        #pragma unroll
        for (int k = 0; k < PPT; ++k) {
            // bits = 0x4B000000 + floor(x*4096), exact (RZ fma, positive sum)
            int bi = (int)__float_as_uint(__fmaf_rz(x[k], 4096.0f, 8388608.0f));
            bi = max(bi, 0x4B000000);          // x < 0  -> cell 0
            bi = min(bi, 0x4B000FFF);          // x >= 1 -> cell 31
            // addr = base | slot*8 | cell*128  (single LOP3)
            uint32_t addr = ((uint32_t)bi & 0x0F80u) | C;
            float t0, t1;
            asm volatile("ld.shared.v2.f32 {%0,%1}, [%2];"
                         : "=f"(t0), "=f"(t1) : "r"(addr));
            x[k] = fmaf(t0, x[k], t1);
        }
    }

    float* __restrict__ o = out + (size_t)t * (size_t)n_points;
    #pragma unroll
    for (int k = 0; k < PPT; ++k) {
        int idx = base + k * BLOCK;
        if (idx < n_points) o[idx] = x[k];
    }
}

extern "C" void kernel_launch(void* const* d_in, const int* in_sizes, int n_in,
                              void* d_out, int out_size)
{
    const float* points = (const float*)d_in[0];  // [1, n_points]
    const float* theta  = (const float*)d_in[1];  // [n_theta, 30]
    const float* basis  = (const float*)d_in[2];  // [64, 30]
    float* out = (float*)d_out;                   // [n_theta, 1, n_points]

    const int n_points = in_sizes[0];
    const int n_theta  = in_sizes[1] / DDIM;

    dim3 grid((n_points + BLOCK * PPT - 1) / (BLOCK * PPT), n_theta);
    cpab_kernel<<<grid, BLOCK>>>(points, theta, basis, out, n_points);
}

// round 8
// speedup vs baseline: 1.1627x; 1.1627x over previous
#include <cuda_runtime.h>
#include <cstdint>

#define NC      32
#define NSTEPS  32
#define DDIM    30
#define BLOCK   256
#define PPT     8     // independent chains per thread

__global__ __launch_bounds__(BLOCK)
void cpab_kernel(const float* __restrict__ points,
                 const float* __restrict__ theta,
                 const float* __restrict__ basis,
                 float* __restrict__ out,
                 int n_points)
{
    __shared__ float s0[NC];
    __shared__ float s1[NC];

    const int t    = blockIdx.y;
    const int tid  = threadIdx.x;
    const int lane = tid & 31;

    // --- 32 per-cell step transforms for this theta ---
    if (tid < NC) {
        const float dT = 1.0f / (float)NSTEPS;
        const float* __restrict__ ba = basis + (2 * tid)     * DDIM;
        const float* __restrict__ bb = basis + (2 * tid + 1) * DDIM;
        const float* __restrict__ th = theta + t * DDIM;
        float a = 0.0f, b = 0.0f;
        #pragma unroll
        for (int j = 0; j < DDIM; ++j) {
            float tj = th[j];
            a = fmaf(ba[j], tj, a);
            b = fmaf(bb[j], tj, b);
        }
        a *= dT;
        b *= dT;
        float ea  = expf(a);
        float phi = (fabsf(a) < 1e-6f) ? (1.0f + 0.5f * a) : (expm1f(a) / a);
        s0[tid] = ea;
        s1[tid] = b * phi;
    }
    __syncthreads();

    // Table lives in registers: lane l holds cell l's transform.
    const float T0 = s0[lane];
    const float T1 = s1[lane];

    // --- Main integration: 8 independent chains per thread ---
    const int base = blockIdx.x * (BLOCK * PPT) + tid;

    float x[PPT];
    #pragma unroll
    for (int k = 0; k < PPT; ++k) {
        int idx = base + k * BLOCK;
        x[k] = (idx < n_points) ? points[idx] : 0.0f;
    }

    #pragma unroll 4
    for (int s = 0; s < NSTEPS; ++s) {
        #pragma unroll
        for (int k = 0; k < PPT; ++k) {
            // bits = 0x4B000000 + floor(x*32), exact (RZ fma, positive sum).
            // Low 5 bits of `bi` == cell index; shfl applies srcLane mod 32.
            int bi = (int)__float_as_uint(__fmaf_rz(x[k], 32.0f, 8388608.0f));
            bi = max(bi, 0x4B000000);          // x < 0  -> cell 0
            bi = min(bi, 0x4B00001F);          // x >= 1 -> cell 31
            float t0 = __shfl_sync(0xFFFFFFFFu, T0, bi);
            float t1 = __shfl_sync(0xFFFFFFFFu, T1, bi);
            x[k] = fmaf(t0, x[k], t1);
        }
    }

    float* __restrict__ o = out + (size_t)t * (size_t)n_points;
    #pragma unroll
    for (int k = 0; k < PPT; ++k) {
        int idx = base + k * BLOCK;
        if (idx < n_points) o[idx] = x[k];
    }
}

extern "C" void kernel_launch(void* const* d_in, const int* in_sizes, int n_in,
                              void* d_out, int out_size)
{
    const float* points = (const float*)d_in[0];  // [1, n_points]
    const float* theta  = (const float*)d_in[1];  // [n_theta, 30]
    const float* basis  = (const float*)d_in[2];  // [64, 30]
    float* out = (float*)d_out;                   // [n_theta, 1, n_points]

    const int n_points = in_sizes[0];
    const int n_theta  = in_sizes[1] / DDIM;

    dim3 grid((n_points + BLOCK * PPT - 1) / (BLOCK * PPT), n_theta);
    cpab_kernel<<<grid, BLOCK>>>(points, theta, basis, out, n_points);
}